// round 4
// baseline (speedup 1.0000x reference)
#include <cuda_runtime.h>
#include <mma.h>
#include <math.h>

using namespace nvcuda;

#define NN    512
#define MEM   1024
#define KD    1024
#define TM3   3072
#define NINT  128
#define IBASE 384
#define NLVL  5
#define LDA   20

// ---------------- scratch (static device allocation, allowed) ----------------
__device__ float g_XI [NN * TM3];          // x @ ioux_w^T           (no bias)
__device__ float g_XF [NINT * MEM];        // x @ fx_w^T             (no bias)
__device__ float g_c  [NN * MEM];          // cell states
__device__ float g_FH [(NN + 128) * MEM];  // h @ fh_w^T (padded, no bias)
__device__ float g_hs [NINT * MEM];        // child-sum of h
__device__ float g_t  [NINT * MEM];        // W_rel-transformed child-sum
__device__ float g_IOU[128 * TM3];         // per-level t @ iouh_w^T (padded)
__device__ int   g_grp_nodes[NLVL][64];
__device__ int   g_grp_start[NLVL][50];

__device__ __forceinline__ float sigm(float v) {
    return __fdividef(1.0f, 1.0f + __expf(-v));
}
__device__ __forceinline__ float ftanh(float v) {
    return 1.0f - __fdividef(2.0f, __expf(2.0f * v) + 1.0f);
}

// ============ tf32 GEMM: C[m,n] = sum_k A[m,k]*B[n,k]  (NO bias) =============
// BM=BN=128, BK=16. 256 threads = 8 warps (2x4), warp tile 64x32 (4x2 wmma).
// A loads guarded by M (zero fill). Stores UNGUARDED -> C padded to 128 rows.
__global__ void __launch_bounds__(256) gemm_tc(const float* __restrict__ A,
                                               const float* __restrict__ B,
                                               float* __restrict__ C,
                                               int M, int N, int K)
{
    __shared__ float As[128 * LDA];
    __shared__ float Bs[128 * LDA];

    int tid = threadIdx.x;
    int wid = tid >> 5;
    int wm  = wid >> 2, wn = wid & 3;
    int m0  = blockIdx.y * 128, n0 = blockIdx.x * 128;
    int row = tid >> 2;
    int c0  = (tid & 3) * 4;

    wmma::fragment<wmma::accumulator, 16, 16, 8, float> acc[4][2];
    #pragma unroll
    for (int i = 0; i < 4; i++)
        #pragma unroll
        for (int j = 0; j < 2; j++)
            wmma::fill_fragment(acc[i][j], 0.0f);

    const float4 z4 = make_float4(0.f, 0.f, 0.f, 0.f);
    int gm0 = m0 + row, gm1 = m0 + 64 + row;
    const float* A0 = A + (size_t)gm0 * K + c0;
    const float* A1 = A + (size_t)gm1 * K + c0;
    const float* B0 = B + (size_t)(n0 + row) * K + c0;
    const float* B1 = B + (size_t)(n0 + 64 + row) * K + c0;

    float4 ar0 = (gm0 < M) ? *(const float4*)A0 : z4;
    float4 ar1 = (gm1 < M) ? *(const float4*)A1 : z4;
    float4 br0 = *(const float4*)B0;
    float4 br1 = *(const float4*)B1;

    for (int k0 = 0; k0 < K; k0 += 16) {
        float* a0 = &As[row * LDA + c0];
        a0[0] = wmma::__float_to_tf32(ar0.x); a0[1] = wmma::__float_to_tf32(ar0.y);
        a0[2] = wmma::__float_to_tf32(ar0.z); a0[3] = wmma::__float_to_tf32(ar0.w);
        float* a1 = &As[(row + 64) * LDA + c0];
        a1[0] = wmma::__float_to_tf32(ar1.x); a1[1] = wmma::__float_to_tf32(ar1.y);
        a1[2] = wmma::__float_to_tf32(ar1.z); a1[3] = wmma::__float_to_tf32(ar1.w);
        float* b0 = &Bs[row * LDA + c0];
        b0[0] = wmma::__float_to_tf32(br0.x); b0[1] = wmma::__float_to_tf32(br0.y);
        b0[2] = wmma::__float_to_tf32(br0.z); b0[3] = wmma::__float_to_tf32(br0.w);
        float* b1 = &Bs[(row + 64) * LDA + c0];
        b1[0] = wmma::__float_to_tf32(br1.x); b1[1] = wmma::__float_to_tf32(br1.y);
        b1[2] = wmma::__float_to_tf32(br1.z); b1[3] = wmma::__float_to_tf32(br1.w);
        __syncthreads();

        if (k0 + 16 < K) {
            int kn = k0 + 16;
            ar0 = (gm0 < M) ? *(const float4*)(A0 + kn) : z4;
            ar1 = (gm1 < M) ? *(const float4*)(A1 + kn) : z4;
            br0 = *(const float4*)(B0 + kn);
            br1 = *(const float4*)(B1 + kn);
        }

        #pragma unroll
        for (int kk = 0; kk < 2; kk++) {
            wmma::fragment<wmma::matrix_a, 16, 16, 8, wmma::precision::tf32, wmma::row_major> af[4];
            wmma::fragment<wmma::matrix_b, 16, 16, 8, wmma::precision::tf32, wmma::col_major> bf[2];
            #pragma unroll
            for (int i = 0; i < 4; i++)
                wmma::load_matrix_sync(af[i], &As[(wm * 64 + i * 16) * LDA + kk * 8], LDA);
            #pragma unroll
            for (int j = 0; j < 2; j++)
                wmma::load_matrix_sync(bf[j], &Bs[(wn * 32 + j * 16) * LDA + kk * 8], LDA);
            #pragma unroll
            for (int i = 0; i < 4; i++)
                #pragma unroll
                for (int j = 0; j < 2; j++)
                    wmma::mma_sync(acc[i][j], af[i], bf[j], acc[i][j]);
        }
        __syncthreads();
    }

    #pragma unroll
    for (int i = 0; i < 4; i++)
        #pragma unroll
        for (int j = 0; j < 2; j++) {
            float* Cp = C + (size_t)(m0 + wm * 64 + i * 16) * N + n0 + wn * 32 + j * 16;
            wmma::store_matrix_sync(Cp, acc[i][j], N, wmma::mem_row_major);
        }
}

// ---------------- leaves: nodes 0..383, pure elementwise from XI -------------
__global__ void leaf_k(float* __restrict__ h,
                       const float* __restrict__ ioux_b,
                       const float* __restrict__ iouh_b)
{
    int node = blockIdx.y;
    int j = blockIdx.x * 256 + threadIdx.x;
    const float* xi = g_XI + (size_t)node * TM3;
    float ig = sigm(xi[j] + ioux_b[j] + iouh_b[j]);
    float og = sigm(xi[MEM + j] + ioux_b[MEM + j] + iouh_b[MEM + j]);
    float ug = ftanh(xi[2 * MEM + j] + ioux_b[2 * MEM + j] + iouh_b[2 * MEM + j]);
    float cv = ig * ug;
    g_c[(size_t)node * MEM + j] = cv;
    h[(size_t)node * MEM + j] = og * ftanh(cv);
}

// ---------------- one-time device-side grouping by relation ------------------
__global__ void prep_groups(const int* __restrict__ rel_ids)
{
    const int lvl_n0[NLVL]  = {384, 427, 491, 507, 511};
    const int lvl_cnt[NLVL] = { 43,  64,  16,   4,   1};
    for (int L = 0; L < NLVL; L++) {
        int cnt_r[49];
        for (int r = 0; r < 49; r++) cnt_r[r] = 0;
        int n0 = lvl_n0[L], cnt = lvl_cnt[L];
        for (int i = 0; i < cnt; i++) cnt_r[rel_ids[n0 + i]]++;
        int acc = 0;
        for (int r = 0; r < 49; r++) { g_grp_start[L][r] = acc; acc += cnt_r[r]; }
        g_grp_start[L][49] = acc;
        int pos[49];
        for (int r = 0; r < 49; r++) pos[r] = g_grp_start[L][r];
        for (int i = 0; i < cnt; i++) {
            int r = rel_ids[n0 + i];
            g_grp_nodes[L][pos[r]++] = n0 + i - IBASE;
        }
    }
}

// ---------------- child-sum of h for one level of internal nodes -------------
__global__ void csum_k(const float* __restrict__ h,
                       const int* __restrict__ child_idx, int n0)
{
    int node = n0 + blockIdx.y;
    int j = blockIdx.x * 256 + threadIdx.x;
    const int* ci = child_idx + node * 4;
    float s = 0.f;
    #pragma unroll
    for (int k = 0; k < 4; k++) {
        int c = ci[k];
        if (c >= 0) s += h[(size_t)c * MEM + j];
    }
    g_hs[(size_t)(node - IBASE) * MEM + j] = s;
}

// -------- t = hs @ Wrel[rel]^T, grouped by rel: W read once per group --------
__global__ void __launch_bounds__(256) wrel_grp(const float* __restrict__ Wrel, int lvl)
{
    int r  = blockIdx.y;
    int s0 = g_grp_start[lvl][r];
    int g  = g_grp_start[lvl][r + 1] - s0;
    if (g == 0) return;
    __shared__ float sh[MEM];
    int lane = threadIdx.x & 31, wid = threadIdx.x >> 5;
    int row = blockIdx.x * 8 + wid;
    const float* W = Wrel + (size_t)r * (MEM * MEM) + (size_t)row * MEM;
    float4 w[8];
    #pragma unroll
    for (int i = 0; i < 8; i++) w[i] = *(const float4*)(W + (i * 32 + lane) * 4);
    for (int j = 0; j < g; j++) {
        int li = g_grp_nodes[lvl][s0 + j];
        for (int i = threadIdx.x; i < MEM / 4; i += 256)
            ((float4*)sh)[i] = ((const float4*)(g_hs + (size_t)li * MEM))[i];
        __syncthreads();
        float s = 0.f;
        #pragma unroll
        for (int i = 0; i < 8; i++) {
            int k4 = (i * 32 + lane) * 4;
            s += w[i].x * sh[k4] + w[i].y * sh[k4 + 1]
               + w[i].z * sh[k4 + 2] + w[i].w * sh[k4 + 3];
        }
        #pragma unroll
        for (int o = 16; o; o >>= 1) s += __shfl_xor_sync(0xffffffffu, s, o);
        if (lane == 0) g_t[(size_t)li * MEM + row] = s;
        __syncthreads();
    }
}

// --- fused: fc from children + gates -> h, c (biases applied here) -----------
__global__ void cellfc_k(float* __restrict__ h,
                         const int* __restrict__ child_idx,
                         const float* __restrict__ ioux_b,
                         const float* __restrict__ iouh_b,
                         const float* __restrict__ fx_b,
                         const float* __restrict__ fh_b, int n0)
{
    int node = n0 + blockIdx.y;
    int li = node - IBASE;
    int j = blockIdx.x * 256 + threadIdx.x;
    const int* ci = child_idx + node * 4;
    float base = g_XF[(size_t)li * MEM + j] + fx_b[j] + fh_b[j];
    float fc = 0.f;
    #pragma unroll
    for (int k = 0; k < 4; k++) {
        int c = ci[k];
        if (c >= 0)
            fc += sigm(g_FH[(size_t)c * MEM + j] + base) * g_c[(size_t)c * MEM + j];
    }
    const float* io = g_IOU + (size_t)blockIdx.y * TM3;
    const float* xi = g_XI + (size_t)node * TM3;
    float ig = sigm(io[j] + xi[j] + ioux_b[j] + iouh_b[j]);
    float og = sigm(io[MEM + j] + xi[MEM + j] + ioux_b[MEM + j] + iouh_b[MEM + j]);
    float ug = ftanh(io[2 * MEM + j] + xi[2 * MEM + j] + ioux_b[2 * MEM + j] + iouh_b[2 * MEM + j]);
    float cv = ig * ug + fc;
    g_c[(size_t)node * MEM + j] = cv;
    h[(size_t)node * MEM + j] = og * ftanh(cv);
}

// ------------------------------- launcher ------------------------------------
extern "C" void kernel_launch(void* const* d_in, const int* in_sizes, int n_in,
                              void* d_out, int out_size)
{
    const float* x       = (const float*)d_in[0];
    const float* Wrel    = (const float*)d_in[1];
    const float* ioux_w  = (const float*)d_in[2];
    const float* ioux_b  = (const float*)d_in[3];
    const float* iouh_w  = (const float*)d_in[4];
    const float* iouh_b  = (const float*)d_in[5];
    const float* fx_w    = (const float*)d_in[6];
    const float* fx_b    = (const float*)d_in[7];
    const float* fh_w    = (const float*)d_in[8];
    const float* fh_b    = (const float*)d_in[9];
    const int*   child_idx = (const int*)d_in[10];
    const int*   rel_ids   = (const int*)d_in[11];
    float* h = (float*)d_out;

    float *p_XI, *p_XF, *p_FH, *p_t, *p_IOU;
    cudaGetSymbolAddress((void**)&p_XI,  g_XI);
    cudaGetSymbolAddress((void**)&p_XF,  g_XF);
    cudaGetSymbolAddress((void**)&p_FH,  g_FH);
    cudaGetSymbolAddress((void**)&p_t,   g_t);
    cudaGetSymbolAddress((void**)&p_IOU, g_IOU);

    prep_groups<<<1, 1>>>(rel_ids);

    // hoisted projections (tf32 tensor cores, bias-free)
    gemm_tc<<<dim3(TM3 / 128, NN / 128), 256>>>(x, ioux_w, p_XI, NN, TM3, KD);
    gemm_tc<<<dim3(MEM / 128, 1), 256>>>(x + (size_t)IBASE * KD, fx_w, p_XF,
                                         NINT, MEM, KD);

    // leaves + their forget-gate projection
    leaf_k<<<dim3(4, 384), 256>>>(h, ioux_b, iouh_b);
    gemm_tc<<<dim3(MEM / 128, 3), 256>>>(h, fh_w, p_FH, 384, MEM, MEM);

    const int lvl_n0[NLVL]  = {384, 427, 491, 507, 511};
    const int lvl_cnt[NLVL] = { 43,  64,  16,   4,   1};
    for (int L = 0; L < NLVL; L++) {
        int n0 = lvl_n0[L], cnt = lvl_cnt[L];
        csum_k<<<dim3(4, cnt), 256>>>(h, child_idx, n0);
        wrel_grp<<<dim3(128, 49), 256>>>(Wrel, L);
        gemm_tc<<<dim3(TM3 / 128, 1), 256>>>(p_t + (size_t)(n0 - IBASE) * MEM,
                                             iouh_w, p_IOU, cnt, TM3, MEM);
        cellfc_k<<<dim3(4, cnt), 256>>>(h, child_idx, ioux_b, iouh_b,
                                        fx_b, fh_b, n0);
        if (L < NLVL - 1)
            gemm_tc<<<dim3(MEM / 128, 1), 256>>>(h + (size_t)n0 * MEM, fh_w,
                                                 p_FH + (size_t)n0 * MEM,
                                                 cnt, MEM, MEM);
    }
}

// round 6
// speedup vs baseline: 2.3720x; 2.3720x over previous
#include <cuda_runtime.h>
#include <math.h>
#include <stdint.h>

#define NN    512
#define MEM   1024
#define KD    1024
#define TM3   3072
#define NINT  128
#define IBASE 384
#define NLVL  5

// ---------------- fp32 scratch ----------------
__device__ float g_XI [NN * TM3];          // x @ ioux_w^T   (no bias)
__device__ float g_XF [NINT * MEM];        // x @ fx_w^T     (no bias)
__device__ float g_c  [NN * MEM];          // cell states
__device__ float g_FH [(NN + 128) * MEM];  // h @ fh_w^T     (padded rows)
__device__ float g_hs [NINT * MEM];        // child-sum of h
__device__ float g_IOU[64 * TM3];          // per-level t @ iouh_w^T (padded)
__device__ int   g_grp_nodes[NLVL][64];
__device__ int   g_grp_start[NLVL][50];

// ---------------- tf32-rounded operand copies ----------------
__device__ float g_x32  [NN * KD];
__device__ float g_ioxw32[TM3 * KD];
__device__ float g_iohw32[TM3 * MEM];
__device__ float g_fxw32[MEM * KD];
__device__ float g_fhw32[MEM * MEM];
__device__ float g_h32 [640 * MEM];        // padded: level FH reads up to row 570
__device__ float g_t32 [256 * MEM];        // padded: level IOU reads up to row 190

__device__ __forceinline__ float sigm(float v) {
    return __fdividef(1.0f, 1.0f + __expf(-v));
}
__device__ __forceinline__ float ftanh(float v) {
    return 1.0f - __fdividef(2.0f, __expf(2.0f * v) + 1.0f);
}
__device__ __forceinline__ float to_tf32(float x) {
    uint32_t u;
    asm("cvt.rna.tf32.f32 %0, %1;" : "=r"(u) : "f"(x));
    return __uint_as_float(u);
}

// =================== async-copy / mma helpers (compute_103-safe) =============
__device__ __forceinline__ uint32_t s2u(const void* p) {
    uint32_t a;
    asm("{ .reg .u64 t; cvta.to.shared.u64 t, %1; cvt.u32.u64 %0, t; }"
        : "=r"(a) : "l"(p));
    return a;
}
__device__ __forceinline__ void cpa16(uint32_t dst, const void* src) {
    asm volatile("cp.async.cg.shared.global [%0], [%1], 16;"
                 :: "r"(dst), "l"(src) : "memory");
}
__device__ __forceinline__ void cpa_commit() {
    asm volatile("cp.async.commit_group;" ::: "memory");
}
__device__ __forceinline__ void cpa_wait1() {
    asm volatile("cp.async.wait_group 1;" ::: "memory");
}
__device__ __forceinline__ void cpa_wait0() {
    asm volatile("cp.async.wait_group 0;" ::: "memory");
}
__device__ __forceinline__ void mma8(float* c, const uint32_t* a, const uint32_t* b) {
    asm volatile(
        "mma.sync.aligned.m16n8k8.row.col.f32.tf32.tf32.f32 "
        "{%0,%1,%2,%3}, {%4,%5,%6,%7}, {%8,%9}, {%0,%1,%2,%3};"
        : "+f"(c[0]), "+f"(c[1]), "+f"(c[2]), "+f"(c[3])
        : "r"(a[0]), "r"(a[1]), "r"(a[2]), "r"(a[3]), "r"(b[0]), "r"(b[1]));
}

// ========== tf32 mma.sync GEMM: C[m,n] = sum_k A[m,k] * B[n,k] ==============
// BM x 128 tile, BK=32, double-buffered cp.async, 256 thr / 8 warps (2x4),
// warp tile (BM/2) x 32 of m16n8k8. No guards: A must have >= BM-rounded rows
// readable from base; C padded likewise. Operands pre-rounded to tf32.
#define SMSTRIDE 36
template<int BM>
__global__ void __launch_bounds__(256) gemm_mma(const float* __restrict__ A,
                                                const float* __restrict__ B,
                                                float* __restrict__ C,
                                                int N, int K)
{
    constexpr int WM = BM / 2;       // warp rows
    constexpr int MF = BM / 32;      // m16 frags per warp
    constexpr int ASZ = BM * SMSTRIDE;
    constexpr int BSZ = 128 * SMSTRIDE;

    extern __shared__ float sm[];
    float* smA[2] = { sm, sm + ASZ };
    float* smB[2] = { sm + 2 * ASZ, sm + 2 * ASZ + BSZ };
    uint32_t uA[2] = { s2u(smA[0]), s2u(smA[1]) };
    uint32_t uB[2] = { s2u(smB[0]), s2u(smB[1]) };

    int tid = threadIdx.x;
    int lane = tid & 31, wid = tid >> 5;
    int wm = wid >> 2, wn = wid & 3;
    int gr = lane >> 2, qc = lane & 3;
    int m0 = blockIdx.y * BM, n0 = blockIdx.x * 128;

    const float* Abase = A + (size_t)m0 * K;
    const float* Bbase = B + (size_t)n0 * K;

    float cacc[MF][4][4];
    #pragma unroll
    for (int i = 0; i < MF; i++)
        #pragma unroll
        for (int j = 0; j < 4; j++)
            #pragma unroll
            for (int e = 0; e < 4; e++) cacc[i][j][e] = 0.f;

    const int NCH = K >> 5;

    auto load_chunk = [&](int c, int buf) {
        const float* Ap = Abase + c * 32;
        const float* Bp = Bbase + c * 32;
        #pragma unroll
        for (int i = 0; i < BM / 32; i++) {           // BM*8/256 float4 each
            int id = tid + i * 256;
            int row = id >> 3, c4 = (id & 7) << 2;
            cpa16(uA[buf] + (row * SMSTRIDE + c4) * 4, Ap + (size_t)row * K + c4);
        }
        #pragma unroll
        for (int i = 0; i < 4; i++) {
            int id = tid + i * 256;
            int row = id >> 3, c4 = (id & 7) << 2;
            cpa16(uB[buf] + (row * SMSTRIDE + c4) * 4, Bp + (size_t)row * K + c4);
        }
        cpa_commit();
    };

    load_chunk(0, 0);

    for (int c = 0; c < NCH; c++) {
        int buf = c & 1;
        if (c + 1 < NCH) { load_chunk(c + 1, buf ^ 1); cpa_wait1(); }
        else             { cpa_wait0(); }
        __syncthreads();

        const float* As = smA[buf];
        const float* Bs = smB[buf];
        #pragma unroll
        for (int kk = 0; kk < 4; kk++) {
            int k = kk * 8;
            uint32_t b[4][2];
            #pragma unroll
            for (int ni = 0; ni < 4; ni++) {
                int nr = wn * 32 + ni * 8 + gr;
                b[ni][0] = __float_as_uint(Bs[nr * SMSTRIDE + k + qc]);
                b[ni][1] = __float_as_uint(Bs[nr * SMSTRIDE + k + qc + 4]);
            }
            uint32_t a[MF][4];
            #pragma unroll
            for (int mi = 0; mi < MF; mi++) {
                int mr = wm * WM + mi * 16 + gr;
                a[mi][0] = __float_as_uint(As[mr * SMSTRIDE + k + qc]);
                a[mi][1] = __float_as_uint(As[(mr + 8) * SMSTRIDE + k + qc]);
                a[mi][2] = __float_as_uint(As[mr * SMSTRIDE + k + qc + 4]);
                a[mi][3] = __float_as_uint(As[(mr + 8) * SMSTRIDE + k + qc + 4]);
            }
            #pragma unroll
            for (int mi = 0; mi < MF; mi++)
                #pragma unroll
                for (int ni = 0; ni < 4; ni++)
                    mma8(cacc[mi][ni], a[mi], b[ni]);
        }
        __syncthreads();
    }

    #pragma unroll
    for (int mi = 0; mi < MF; mi++)
        #pragma unroll
        for (int ni = 0; ni < 4; ni++) {
            int row = m0 + wm * WM + mi * 16 + gr;
            int col = n0 + wn * 32 + ni * 8 + qc * 2;
            *(float2*)(C + (size_t)row * N + col) =
                make_float2(cacc[mi][ni][0], cacc[mi][ni][1]);
            *(float2*)(C + (size_t)(row + 8) * N + col) =
                make_float2(cacc[mi][ni][2], cacc[mi][ni][3]);
        }
}

// ---------------- fp32 -> tf32-rounded copy ----------------------------------
__global__ void conv_k(const float* __restrict__ src, float* __restrict__ dst, int n4)
{
    int i = blockIdx.x * 256 + threadIdx.x;
    if (i < n4) {
        float4 v = ((const float4*)src)[i];
        v.x = to_tf32(v.x); v.y = to_tf32(v.y);
        v.z = to_tf32(v.z); v.w = to_tf32(v.w);
        ((float4*)dst)[i] = v;
    }
}

// ---------------- leaves: nodes 0..383 ---------------------------------------
__global__ void leaf_k(float* __restrict__ h,
                       const float* __restrict__ ioux_b,
                       const float* __restrict__ iouh_b)
{
    int node = blockIdx.y;
    int j = blockIdx.x * 256 + threadIdx.x;
    const float* xi = g_XI + (size_t)node * TM3;
    float ig = sigm(xi[j] + ioux_b[j] + iouh_b[j]);
    float og = sigm(xi[MEM + j] + ioux_b[MEM + j] + iouh_b[MEM + j]);
    float ug = ftanh(xi[2 * MEM + j] + ioux_b[2 * MEM + j] + iouh_b[2 * MEM + j]);
    float cv = ig * ug;
    size_t idx = (size_t)node * MEM + j;
    g_c[idx] = cv;
    float hv = og * ftanh(cv);
    h[idx] = hv;
    g_h32[idx] = to_tf32(hv);
}

// ---------------- one-time grouping by relation ------------------------------
__global__ void prep_groups(const int* __restrict__ rel_ids)
{
    const int lvl_n0[NLVL]  = {384, 427, 491, 507, 511};
    const int lvl_cnt[NLVL] = { 43,  64,  16,   4,   1};
    for (int L = 0; L < NLVL; L++) {
        int cnt_r[49];
        for (int r = 0; r < 49; r++) cnt_r[r] = 0;
        int n0 = lvl_n0[L], cnt = lvl_cnt[L];
        for (int i = 0; i < cnt; i++) cnt_r[rel_ids[n0 + i]]++;
        int acc = 0;
        for (int r = 0; r < 49; r++) { g_grp_start[L][r] = acc; acc += cnt_r[r]; }
        g_grp_start[L][49] = acc;
        int pos[49];
        for (int r = 0; r < 49; r++) pos[r] = g_grp_start[L][r];
        for (int i = 0; i < cnt; i++) {
            int r = rel_ids[n0 + i];
            g_grp_nodes[L][pos[r]++] = n0 + i - IBASE;
        }
    }
}

// ---------------- child-sum of h ---------------------------------------------
__global__ void csum_k(const float* __restrict__ h,
                       const int* __restrict__ child_idx, int n0)
{
    int node = n0 + blockIdx.y;
    int j = blockIdx.x * 256 + threadIdx.x;
    const int* ci = child_idx + node * 4;
    float s = 0.f;
    #pragma unroll
    for (int k = 0; k < 4; k++) {
        int c = ci[k];
        if (c >= 0) s += h[(size_t)c * MEM + j];
    }
    g_hs[(size_t)(node - IBASE) * MEM + j] = s;
}

// -------- t = hs @ Wrel[rel]^T, grouped by rel (tf32-rounded write) ----------
__global__ void __launch_bounds__(256) wrel_grp(const float* __restrict__ Wrel, int lvl)
{
    int r  = blockIdx.y;
    int s0 = g_grp_start[lvl][r];
    int g  = g_grp_start[lvl][r + 1] - s0;
    if (g == 0) return;
    __shared__ float sh[MEM];
    int lane = threadIdx.x & 31, wid = threadIdx.x >> 5;
    int row = blockIdx.x * 8 + wid;
    const float* W = Wrel + (size_t)r * (MEM * MEM) + (size_t)row * MEM;
    float4 w[8];
    #pragma unroll
    for (int i = 0; i < 8; i++) w[i] = *(const float4*)(W + (i * 32 + lane) * 4);
    for (int j = 0; j < g; j++) {
        int li = g_grp_nodes[lvl][s0 + j];
        for (int i = threadIdx.x; i < MEM / 4; i += 256)
            ((float4*)sh)[i] = ((const float4*)(g_hs + (size_t)li * MEM))[i];
        __syncthreads();
        float s = 0.f;
        #pragma unroll
        for (int i = 0; i < 8; i++) {
            int k4 = (i * 32 + lane) * 4;
            s += w[i].x * sh[k4] + w[i].y * sh[k4 + 1]
               + w[i].z * sh[k4 + 2] + w[i].w * sh[k4 + 3];
        }
        #pragma unroll
        for (int o = 16; o; o >>= 1) s += __shfl_xor_sync(0xffffffffu, s, o);
        if (lane == 0) g_t32[(size_t)li * MEM + row] = to_tf32(s);
        __syncthreads();
    }
}

// --- fused: fc from children + gates -> h, c ---------------------------------
__global__ void cellfc_k(float* __restrict__ h,
                         const int* __restrict__ child_idx,
                         const float* __restrict__ ioux_b,
                         const float* __restrict__ iouh_b,
                         const float* __restrict__ fx_b,
                         const float* __restrict__ fh_b, int n0)
{
    int node = n0 + blockIdx.y;
    int li = node - IBASE;
    int j = blockIdx.x * 256 + threadIdx.x;
    const int* ci = child_idx + node * 4;
    float base = g_XF[(size_t)li * MEM + j] + fx_b[j] + fh_b[j];
    float fc = 0.f;
    #pragma unroll
    for (int k = 0; k < 4; k++) {
        int c = ci[k];
        if (c >= 0)
            fc += sigm(g_FH[(size_t)c * MEM + j] + base) * g_c[(size_t)c * MEM + j];
    }
    const float* io = g_IOU + (size_t)blockIdx.y * TM3;
    const float* xi = g_XI + (size_t)node * TM3;
    float ig = sigm(io[j] + xi[j] + ioux_b[j] + iouh_b[j]);
    float og = sigm(io[MEM + j] + xi[MEM + j] + ioux_b[MEM + j] + iouh_b[MEM + j]);
    float ug = ftanh(io[2 * MEM + j] + xi[2 * MEM + j]
                     + ioux_b[2 * MEM + j] + iouh_b[2 * MEM + j]);
    float cv = ig * ug + fc;
    size_t idx = (size_t)node * MEM + j;
    g_c[idx] = cv;
    float hv = og * ftanh(cv);
    h[idx] = hv;
    g_h32[idx] = to_tf32(hv);
}

// ------------------------------- launcher ------------------------------------
extern "C" void kernel_launch(void* const* d_in, const int* in_sizes, int n_in,
                              void* d_out, int out_size)
{
    const float* x       = (const float*)d_in[0];
    const float* Wrel    = (const float*)d_in[1];
    const float* ioux_w  = (const float*)d_in[2];
    const float* ioux_b  = (const float*)d_in[3];
    const float* iouh_w  = (const float*)d_in[4];
    const float* iouh_b  = (const float*)d_in[5];
    const float* fx_w    = (const float*)d_in[6];
    const float* fx_b    = (const float*)d_in[7];
    const float* fh_w    = (const float*)d_in[8];
    const float* fh_b    = (const float*)d_in[9];
    const int*   child_idx = (const int*)d_in[10];
    const int*   rel_ids   = (const int*)d_in[11];
    float* h = (float*)d_out;

    const int SM128 = (2 * 128 * SMSTRIDE + 2 * 128 * SMSTRIDE) * 4;  // 73728 B
    const int SM64  = (2 * 64 * SMSTRIDE + 2 * 128 * SMSTRIDE) * 4;   // 55296 B
    cudaFuncSetAttribute(gemm_mma<128>, cudaFuncAttributeMaxDynamicSharedMemorySize, SM128);
    cudaFuncSetAttribute(gemm_mma<64>,  cudaFuncAttributeMaxDynamicSharedMemorySize, SM64);

    float *p_XI, *p_XF, *p_FH, *p_IOU;
    float *p_x32, *p_ioxw32, *p_iohw32, *p_fxw32, *p_fhw32, *p_h32, *p_t32;
    cudaGetSymbolAddress((void**)&p_XI,  g_XI);
    cudaGetSymbolAddress((void**)&p_XF,  g_XF);
    cudaGetSymbolAddress((void**)&p_FH,  g_FH);
    cudaGetSymbolAddress((void**)&p_IOU, g_IOU);
    cudaGetSymbolAddress((void**)&p_x32,   g_x32);
    cudaGetSymbolAddress((void**)&p_ioxw32, g_ioxw32);
    cudaGetSymbolAddress((void**)&p_iohw32, g_iohw32);
    cudaGetSymbolAddress((void**)&p_fxw32, g_fxw32);
    cudaGetSymbolAddress((void**)&p_fhw32, g_fhw32);
    cudaGetSymbolAddress((void**)&p_h32, g_h32);
    cudaGetSymbolAddress((void**)&p_t32, g_t32);

    prep_groups<<<1, 1>>>(rel_ids);

    conv_k<<<(NN * KD / 4 + 255) / 256, 256>>>(x, p_x32, NN * KD / 4);
    conv_k<<<(TM3 * KD / 4 + 255) / 256, 256>>>(ioux_w, p_ioxw32, TM3 * KD / 4);
    conv_k<<<(TM3 * MEM / 4 + 255) / 256, 256>>>(iouh_w, p_iohw32, TM3 * MEM / 4);
    conv_k<<<(MEM * KD / 4 + 255) / 256, 256>>>(fx_w, p_fxw32, MEM * KD / 4);
    conv_k<<<(MEM * MEM / 4 + 255) / 256, 256>>>(fh_w, p_fhw32, MEM * MEM / 4);

    // XI = x @ ioux_w^T   (512 x 3072, K=1024)
    gemm_mma<128><<<dim3(TM3 / 128, NN / 128), 256, SM128>>>(p_x32, p_ioxw32, p_XI, TM3, KD);
    // XF = x[384:] @ fx_w^T   (128 x 1024)
    gemm_mma<128><<<dim3(MEM / 128, 1), 256, SM128>>>(p_x32 + (size_t)IBASE * KD,
                                                      p_fxw32, p_XF, MEM, KD);

    leaf_k<<<dim3(4, 384), 256>>>(h, ioux_b, iouh_b);
    // FH for leaves (384 x 1024)
    gemm_mma<128><<<dim3(MEM / 128, 3), 256, SM128>>>(p_h32, p_fhw32, p_FH, MEM, MEM);

    const int lvl_n0[NLVL]  = {384, 427, 491, 507, 511};
    const int lvl_cnt[NLVL] = { 43,  64,  16,   4,   1};
    for (int L = 0; L < NLVL; L++) {
        int n0 = lvl_n0[L], cnt = lvl_cnt[L];
        csum_k<<<dim3(4, cnt), 256>>>(h, child_idx, n0);
        wrel_grp<<<dim3(128, 49), 256>>>(Wrel, L);
        // IOU = t_lvl @ iouh_w^T   (pad M to 64)
        gemm_mma<64><<<dim3(TM3 / 128, 1), 256, SM64>>>(
            p_t32 + (size_t)(n0 - IBASE) * MEM, p_iohw32, p_IOU, TM3, MEM);
        cellfc_k<<<dim3(4, cnt), 256>>>(h, child_idx, ioux_b, iouh_b, fx_b, fh_b, n0);
        if (L < NLVL - 1)   // FH for this level's nodes (pad M to 64)
            gemm_mma<64><<<dim3(MEM / 128, 1), 256, SM64>>>(
                p_h32 + (size_t)n0 * MEM, p_fhw32,
                p_FH + (size_t)n0 * MEM, MEM, MEM);
    }
}

// round 7
// speedup vs baseline: 4.2215x; 1.7798x over previous
#include <cuda_runtime.h>
#include <math.h>
#include <stdint.h>

#define NN    512
#define MEM   1024
#define KD    1024
#define TM3   3072
#define NINT  128
#define IBASE 384
#define NLVL  5

// ---------------- scratch (static device allocation, allowed) ----------------
// split-K partial slabs
__device__ float g_XIp [2 * NN * TM3];      // x @ ioux_w^T, 2 K-slices
__device__ float g_XFp [4 * NINT * MEM];    // x @ fx_w^T,   4 K-slices
__device__ float g_FHp [4 * 640 * MEM];     // h @ fh_w^T,   4 K-slices (padded rows)
__device__ float g_IOUp[4 * 64 * TM3];      // t_lvl @ iouh_w^T, 4 K-slices
__device__ float g_c   [NN * MEM];          // cell states
__device__ int   g_grp_nodes[NLVL][64];
__device__ int   g_grp_start[NLVL][50];

// tf32-rounded operand copies
__device__ float g_x32   [NN * KD];
__device__ float g_ioxw32[TM3 * KD];
__device__ float g_iohw32[TM3 * MEM];
__device__ float g_fxw32 [MEM * KD];
__device__ float g_fhw32 [MEM * MEM];
__device__ float g_h32   [640 * MEM];       // padded (level FH reads up to row 571)
__device__ float g_t32   [256 * MEM];       // padded (level IOU reads up to row 191)

__device__ __forceinline__ float sigm(float v) {
    return __fdividef(1.0f, 1.0f + __expf(-v));
}
__device__ __forceinline__ float ftanh(float v) {
    return 1.0f - __fdividef(2.0f, __expf(2.0f * v) + 1.0f);
}
__device__ __forceinline__ float to_tf32(float x) {
    uint32_t u;
    asm("cvt.rna.tf32.f32 %0, %1;" : "=r"(u) : "f"(x));
    return __uint_as_float(u);
}

// =================== async-copy / mma helpers ================================
__device__ __forceinline__ uint32_t s2u(const void* p) {
    uint32_t a;
    asm("{ .reg .u64 t; cvta.to.shared.u64 t, %1; cvt.u32.u64 %0, t; }"
        : "=r"(a) : "l"(p));
    return a;
}
__device__ __forceinline__ void cpa16(uint32_t dst, const void* src) {
    asm volatile("cp.async.cg.shared.global [%0], [%1], 16;"
                 :: "r"(dst), "l"(src) : "memory");
}
__device__ __forceinline__ void cpa_commit() {
    asm volatile("cp.async.commit_group;" ::: "memory");
}
__device__ __forceinline__ void cpa_wait1() {
    asm volatile("cp.async.wait_group 1;" ::: "memory");
}
__device__ __forceinline__ void cpa_wait0() {
    asm volatile("cp.async.wait_group 0;" ::: "memory");
}
__device__ __forceinline__ void mma8(float* c, const uint32_t* a, const uint32_t* b) {
    asm volatile(
        "mma.sync.aligned.m16n8k8.row.col.f32.tf32.tf32.f32 "
        "{%0,%1,%2,%3}, {%4,%5,%6,%7}, {%8,%9}, {%0,%1,%2,%3};"
        : "+f"(c[0]), "+f"(c[1]), "+f"(c[2]), "+f"(c[3])
        : "r"(a[0]), "r"(a[1]), "r"(a[2]), "r"(a[3]), "r"(b[0]), "r"(b[1]));
}

// ===== tf32 mma.sync split-K GEMM: Cp[z] += A[:,z-slice] * B^T[:,z-slice] ====
// BM x 128 tile, BK=32, double-buffered cp.async, 256 thr / 8 warps (2x4).
// blockIdx.z selects K-slice (length Klen); partial written to Cp + z*slab.
// No guards: A must have BM-rounded readable rows; C slabs padded likewise.
#define SMSTRIDE 36
template<int BM>
__global__ void __launch_bounds__(256) gemm_mma(const float* __restrict__ A,
                                                const float* __restrict__ B,
                                                float* __restrict__ Cp,
                                                int N, int Kstride, int Klen,
                                                int slab)
{
    constexpr int WM = BM / 2;
    constexpr int MF = BM / 32;
    constexpr int ASZ = BM * SMSTRIDE;
    constexpr int BSZ = 128 * SMSTRIDE;

    extern __shared__ float sm[];
    float* smA[2] = { sm, sm + ASZ };
    float* smB[2] = { sm + 2 * ASZ, sm + 2 * ASZ + BSZ };
    uint32_t uA[2] = { s2u(smA[0]), s2u(smA[1]) };
    uint32_t uB[2] = { s2u(smB[0]), s2u(smB[1]) };

    int tid = threadIdx.x;
    int lane = tid & 31, wid = tid >> 5;
    int wm = wid >> 2, wn = wid & 3;
    int gr = lane >> 2, qc = lane & 3;
    int m0 = blockIdx.y * BM, n0 = blockIdx.x * 128;
    int koff = blockIdx.z * Klen;

    const float* Abase = A + (size_t)m0 * Kstride + koff;
    const float* Bbase = B + (size_t)n0 * Kstride + koff;
    float* C = Cp + (size_t)blockIdx.z * slab;

    float cacc[MF][4][4];
    #pragma unroll
    for (int i = 0; i < MF; i++)
        #pragma unroll
        for (int j = 0; j < 4; j++)
            #pragma unroll
            for (int e = 0; e < 4; e++) cacc[i][j][e] = 0.f;

    const int NCH = Klen >> 5;

    auto load_chunk = [&](int c, int buf) {
        const float* Ap = Abase + c * 32;
        const float* Bp = Bbase + c * 32;
        #pragma unroll
        for (int i = 0; i < BM / 32; i++) {
            int id = tid + i * 256;
            int row = id >> 3, c4 = (id & 7) << 2;
            cpa16(uA[buf] + (row * SMSTRIDE + c4) * 4, Ap + (size_t)row * Kstride + c4);
        }
        #pragma unroll
        for (int i = 0; i < 4; i++) {
            int id = tid + i * 256;
            int row = id >> 3, c4 = (id & 7) << 2;
            cpa16(uB[buf] + (row * SMSTRIDE + c4) * 4, Bp + (size_t)row * Kstride + c4);
        }
        cpa_commit();
    };

    load_chunk(0, 0);

    for (int c = 0; c < NCH; c++) {
        int buf = c & 1;
        if (c + 1 < NCH) { load_chunk(c + 1, buf ^ 1); cpa_wait1(); }
        else             { cpa_wait0(); }
        __syncthreads();

        const float* As = smA[buf];
        const float* Bs = smB[buf];
        #pragma unroll
        for (int kk = 0; kk < 4; kk++) {
            int k = kk * 8;
            uint32_t b[4][2];
            #pragma unroll
            for (int ni = 0; ni < 4; ni++) {
                int nr = wn * 32 + ni * 8 + gr;
                b[ni][0] = __float_as_uint(Bs[nr * SMSTRIDE + k + qc]);
                b[ni][1] = __float_as_uint(Bs[nr * SMSTRIDE + k + qc + 4]);
            }
            uint32_t a[MF][4];
            #pragma unroll
            for (int mi = 0; mi < MF; mi++) {
                int mr = wm * WM + mi * 16 + gr;
                a[mi][0] = __float_as_uint(As[mr * SMSTRIDE + k + qc]);
                a[mi][1] = __float_as_uint(As[(mr + 8) * SMSTRIDE + k + qc]);
                a[mi][2] = __float_as_uint(As[mr * SMSTRIDE + k + qc + 4]);
                a[mi][3] = __float_as_uint(As[(mr + 8) * SMSTRIDE + k + qc + 4]);
            }
            #pragma unroll
            for (int mi = 0; mi < MF; mi++)
                #pragma unroll
                for (int ni = 0; ni < 4; ni++)
                    mma8(cacc[mi][ni], a[mi], b[ni]);
        }
        __syncthreads();
    }

    #pragma unroll
    for (int mi = 0; mi < MF; mi++)
        #pragma unroll
        for (int ni = 0; ni < 4; ni++) {
            int row = m0 + wm * WM + mi * 16 + gr;
            int col = n0 + wn * 32 + ni * 8 + qc * 2;
            *(float2*)(C + (size_t)row * N + col) =
                make_float2(cacc[mi][ni][0], cacc[mi][ni][1]);
            *(float2*)(C + (size_t)(row + 8) * N + col) =
                make_float2(cacc[mi][ni][2], cacc[mi][ni][3]);
        }
}

// ---------------- merged fp32 -> tf32-rounded copy (5 segments) --------------
#define CV_E0 (NN * KD / 4)
#define CV_E1 (CV_E0 + TM3 * KD / 4)
#define CV_E2 (CV_E1 + TM3 * MEM / 4)
#define CV_E3 (CV_E2 + MEM * KD / 4)
#define CV_E4 (CV_E3 + MEM * MEM / 4)
__global__ void conv5_k(const float* __restrict__ x,
                        const float* __restrict__ ioxw,
                        const float* __restrict__ iohw,
                        const float* __restrict__ fxw,
                        const float* __restrict__ fhw)
{
    int i = blockIdx.x * 256 + threadIdx.x;
    const float4* s; float4* d; int k;
    if      (i < CV_E0) { s = (const float4*)x;    d = (float4*)g_x32;    k = i; }
    else if (i < CV_E1) { s = (const float4*)ioxw; d = (float4*)g_ioxw32; k = i - CV_E0; }
    else if (i < CV_E2) { s = (const float4*)iohw; d = (float4*)g_iohw32; k = i - CV_E1; }
    else if (i < CV_E3) { s = (const float4*)fxw;  d = (float4*)g_fxw32;  k = i - CV_E2; }
    else if (i < CV_E4) { s = (const float4*)fhw;  d = (float4*)g_fhw32;  k = i - CV_E3; }
    else return;
    float4 v = s[k];
    v.x = to_tf32(v.x); v.y = to_tf32(v.y);
    v.z = to_tf32(v.z); v.w = to_tf32(v.w);
    d[k] = v;
}

// ---------------- leaves: nodes 0..383 (XI = 2 partial slabs) ----------------
__global__ void leaf_k(float* __restrict__ h,
                       const float* __restrict__ ioux_b,
                       const float* __restrict__ iouh_b)
{
    int node = blockIdx.y;
    int j = blockIdx.x * 256 + threadIdx.x;
    const float* x0 = g_XIp + (size_t)node * TM3;
    const float* x1 = g_XIp + (size_t)NN * TM3 + (size_t)node * TM3;
    float ig = sigm(x0[j] + x1[j] + ioux_b[j] + iouh_b[j]);
    float og = sigm(x0[MEM + j] + x1[MEM + j] + ioux_b[MEM + j] + iouh_b[MEM + j]);
    float ug = ftanh(x0[2 * MEM + j] + x1[2 * MEM + j]
                     + ioux_b[2 * MEM + j] + iouh_b[2 * MEM + j]);
    float cv = ig * ug;
    size_t idx = (size_t)node * MEM + j;
    g_c[idx] = cv;
    float hv = og * ftanh(cv);
    h[idx] = hv;
    g_h32[idx] = to_tf32(hv);
}

// ---------------- one-time grouping by relation ------------------------------
__global__ void prep_groups(const int* __restrict__ rel_ids)
{
    const int lvl_n0[NLVL]  = {384, 427, 491, 507, 511};
    const int lvl_cnt[NLVL] = { 43,  64,  16,   4,   1};
    for (int L = 0; L < NLVL; L++) {
        int cnt_r[49];
        for (int r = 0; r < 49; r++) cnt_r[r] = 0;
        int n0 = lvl_n0[L], cnt = lvl_cnt[L];
        for (int i = 0; i < cnt; i++) cnt_r[rel_ids[n0 + i]]++;
        int acc = 0;
        for (int r = 0; r < 49; r++) { g_grp_start[L][r] = acc; acc += cnt_r[r]; }
        g_grp_start[L][49] = acc;
        int pos[49];
        for (int r = 0; r < 49; r++) pos[r] = g_grp_start[L][r];
        for (int i = 0; i < cnt; i++) {
            int r = rel_ids[n0 + i];
            g_grp_nodes[L][pos[r]++] = n0 + i - IBASE;
        }
    }
}

// --- t = (child-sum of h) @ Wrel[rel]^T, grouped by rel; csum fused in -------
__global__ void __launch_bounds__(256) wrel_grp(const float* __restrict__ Wrel,
                                                const float* __restrict__ h,
                                                const int* __restrict__ child_idx,
                                                int lvl)
{
    int r  = blockIdx.y;
    int s0 = g_grp_start[lvl][r];
    int g  = g_grp_start[lvl][r + 1] - s0;
    if (g == 0) return;
    __shared__ float sh[MEM];
    int lane = threadIdx.x & 31, wid = threadIdx.x >> 5;
    int row = blockIdx.x * 8 + wid;
    const float* W = Wrel + (size_t)r * (MEM * MEM) + (size_t)row * MEM;
    float4 w[8];
    #pragma unroll
    for (int i = 0; i < 8; i++) w[i] = *(const float4*)(W + (i * 32 + lane) * 4);
    for (int j = 0; j < g; j++) {
        int li = g_grp_nodes[lvl][s0 + j];
        int node = li + IBASE;
        const int* ci = child_idx + node * 4;
        int c0 = ci[0], c1 = ci[1], c2 = ci[2], c3 = ci[3];
        {   // fused child-sum (each thread handles one float4 of the 1024-vec)
            int i = threadIdx.x;            // 0..255 == MEM/4
            float4 s = make_float4(0.f, 0.f, 0.f, 0.f);
            if (c0 >= 0) { float4 v = ((const float4*)(h + (size_t)c0 * MEM))[i];
                           s.x += v.x; s.y += v.y; s.z += v.z; s.w += v.w; }
            if (c1 >= 0) { float4 v = ((const float4*)(h + (size_t)c1 * MEM))[i];
                           s.x += v.x; s.y += v.y; s.z += v.z; s.w += v.w; }
            if (c2 >= 0) { float4 v = ((const float4*)(h + (size_t)c2 * MEM))[i];
                           s.x += v.x; s.y += v.y; s.z += v.z; s.w += v.w; }
            if (c3 >= 0) { float4 v = ((const float4*)(h + (size_t)c3 * MEM))[i];
                           s.x += v.x; s.y += v.y; s.z += v.z; s.w += v.w; }
            ((float4*)sh)[i] = s;
        }
        __syncthreads();
        float s = 0.f;
        #pragma unroll
        for (int i = 0; i < 8; i++) {
            int k4 = (i * 32 + lane) * 4;
            s += w[i].x * sh[k4] + w[i].y * sh[k4 + 1]
               + w[i].z * sh[k4 + 2] + w[i].w * sh[k4 + 3];
        }
        #pragma unroll
        for (int o = 16; o; o >>= 1) s += __shfl_xor_sync(0xffffffffu, s, o);
        if (lane == 0) g_t32[(size_t)li * MEM + row] = to_tf32(s);
        __syncthreads();
    }
}

// --- fused: fc from children + gates -> h, c (sums all partial slabs) --------
__global__ void cellfc_k(float* __restrict__ h,
                         const int* __restrict__ child_idx,
                         const float* __restrict__ ioux_b,
                         const float* __restrict__ iouh_b,
                         const float* __restrict__ fx_b,
                         const float* __restrict__ fh_b, int n0)
{
    int node = n0 + blockIdx.y;
    int li = node - IBASE;
    int j = blockIdx.x * 256 + threadIdx.x;
    const int* ci = child_idx + node * 4;

    float xf = 0.f;
    #pragma unroll
    for (int s = 0; s < 4; s++)
        xf += g_XFp[(size_t)s * (NINT * MEM) + (size_t)li * MEM + j];
    float base = xf + fx_b[j] + fh_b[j];

    float fc = 0.f;
    #pragma unroll
    for (int k = 0; k < 4; k++) {
        int c = ci[k];
        if (c >= 0) {
            float fh = 0.f;
            #pragma unroll
            for (int s = 0; s < 4; s++)
                fh += g_FHp[(size_t)s * (640 * MEM) + (size_t)c * MEM + j];
            fc += sigm(fh + base) * g_c[(size_t)c * MEM + j];
        }
    }

    float io0 = 0.f, io1 = 0.f, io2 = 0.f;
    #pragma unroll
    for (int s = 0; s < 4; s++) {
        const float* io = g_IOUp + (size_t)s * (64 * TM3) + (size_t)blockIdx.y * TM3;
        io0 += io[j]; io1 += io[MEM + j]; io2 += io[2 * MEM + j];
    }
    const float* x0 = g_XIp + (size_t)node * TM3;
    const float* x1 = g_XIp + (size_t)NN * TM3 + (size_t)node * TM3;

    float ig = sigm(io0 + x0[j] + x1[j] + ioux_b[j] + iouh_b[j]);
    float og = sigm(io1 + x0[MEM + j] + x1[MEM + j]
                    + ioux_b[MEM + j] + iouh_b[MEM + j]);
    float ug = ftanh(io2 + x0[2 * MEM + j] + x1[2 * MEM + j]
                     + ioux_b[2 * MEM + j] + iouh_b[2 * MEM + j]);
    float cv = ig * ug + fc;
    size_t idx = (size_t)node * MEM + j;
    g_c[idx] = cv;
    float hv = og * ftanh(cv);
    h[idx] = hv;
    g_h32[idx] = to_tf32(hv);
}

// ------------------------------- launcher ------------------------------------
extern "C" void kernel_launch(void* const* d_in, const int* in_sizes, int n_in,
                              void* d_out, int out_size)
{
    const float* x       = (const float*)d_in[0];
    const float* Wrel    = (const float*)d_in[1];
    const float* ioux_w  = (const float*)d_in[2];
    const float* ioux_b  = (const float*)d_in[3];
    const float* iouh_w  = (const float*)d_in[4];
    const float* iouh_b  = (const float*)d_in[5];
    const float* fx_w    = (const float*)d_in[6];
    const float* fx_b    = (const float*)d_in[7];
    const float* fh_w    = (const float*)d_in[8];
    const float* fh_b    = (const float*)d_in[9];
    const int*   child_idx = (const int*)d_in[10];
    const int*   rel_ids   = (const int*)d_in[11];
    float* h = (float*)d_out;

    const int SM128 = (2 * 128 * SMSTRIDE + 2 * 128 * SMSTRIDE) * 4;  // 73728 B
    const int SM64  = (2 * 64 * SMSTRIDE + 2 * 128 * SMSTRIDE) * 4;   // 55296 B
    cudaFuncSetAttribute(gemm_mma<128>, cudaFuncAttributeMaxDynamicSharedMemorySize, SM128);
    cudaFuncSetAttribute(gemm_mma<64>,  cudaFuncAttributeMaxDynamicSharedMemorySize, SM64);

    float *p_XIp, *p_XFp, *p_FHp, *p_IOUp;
    float *p_x32, *p_ioxw32, *p_iohw32, *p_fxw32, *p_fhw32, *p_h32, *p_t32;
    cudaGetSymbolAddress((void**)&p_XIp,  g_XIp);
    cudaGetSymbolAddress((void**)&p_XFp,  g_XFp);
    cudaGetSymbolAddress((void**)&p_FHp,  g_FHp);
    cudaGetSymbolAddress((void**)&p_IOUp, g_IOUp);
    cudaGetSymbolAddress((void**)&p_x32,    g_x32);
    cudaGetSymbolAddress((void**)&p_ioxw32, g_ioxw32);
    cudaGetSymbolAddress((void**)&p_iohw32, g_iohw32);
    cudaGetSymbolAddress((void**)&p_fxw32,  g_fxw32);
    cudaGetSymbolAddress((void**)&p_fhw32,  g_fhw32);
    cudaGetSymbolAddress((void**)&p_h32, g_h32);
    cudaGetSymbolAddress((void**)&p_t32, g_t32);

    prep_groups<<<1, 1>>>(rel_ids);
    conv5_k<<<(CV_E4 + 255) / 256, 256>>>(x, ioux_w, iouh_w, fx_w, fh_w);

    // XI = x @ ioux_w^T  (512x3072, K=1024, split-K x2)
    gemm_mma<128><<<dim3(TM3 / 128, NN / 128, 2), 256, SM128>>>(
        p_x32, p_ioxw32, p_XIp, TM3, KD, 512, NN * TM3);
    // XF = x[384:] @ fx_w^T  (128x1024, split-K x4)
    gemm_mma<128><<<dim3(MEM / 128, 1, 4), 256, SM128>>>(
        p_x32 + (size_t)IBASE * KD, p_fxw32, p_XFp, MEM, KD, 256, NINT * MEM);

    leaf_k<<<dim3(4, 384), 256>>>(h, ioux_b, iouh_b);
    // FH for leaves (384x1024, split-K x4)
    gemm_mma<128><<<dim3(MEM / 128, 3, 4), 256, SM128>>>(
        p_h32, p_fhw32, p_FHp, MEM, MEM, 256, 640 * MEM);

    const int lvl_n0[NLVL]  = {384, 427, 491, 507, 511};
    const int lvl_cnt[NLVL] = { 43,  64,  16,   4,   1};
    for (int L = 0; L < NLVL; L++) {
        int n0 = lvl_n0[L], cnt = lvl_cnt[L];
        wrel_grp<<<dim3(128, 49), 256>>>(Wrel, h, child_idx, L);
        // IOU = t_lvl @ iouh_w^T  (pad M to 64, split-K x4)
        gemm_mma<64><<<dim3(TM3 / 128, 1, 4), 256, SM64>>>(
            p_t32 + (size_t)(n0 - IBASE) * MEM, p_iohw32, p_IOUp,
            TM3, MEM, 256, 64 * TM3);
        cellfc_k<<<dim3(4, cnt), 256>>>(h, child_idx, ioux_b, iouh_b, fx_b, fh_b, n0);
        if (L < NLVL - 1)   // FH for this level's nodes (pad M to 64, split-K x4)
            gemm_mma<64><<<dim3(MEM / 128, 1, 4), 256, SM64>>>(
                p_h32 + (size_t)n0 * MEM, p_fhw32,
                p_FHp + (size_t)n0 * MEM, MEM, MEM, 256, 640 * MEM);
    }
}

// round 8
// speedup vs baseline: 5.8099x; 1.3762x over previous
#include <cuda_runtime.h>
#include <math.h>
#include <stdint.h>

#define NN    512
#define MEM   1024
#define KD    1024
#define TM3   3072
#define NINT  128
#define IBASE 384
#define NLVL  5

// ---------------- scratch (static device allocation, allowed) ----------------
__device__ float g_XIp [2 * NN * TM3];      // x @ ioux_w^T, 2 K-slices
__device__ float g_XFp [4 * NINT * MEM];    // x @ fx_w^T,   4 K-slices
__device__ float g_FHp [4 * 640 * MEM];     // h @ fh_w^T,   4 K-slices (padded rows)
__device__ float g_IOUp[4 * 64 * TM3];      // t_lvl @ iouh_w^T, 4 K-slices
__device__ float g_c   [NN * MEM];          // cell states
__device__ float g_h32 [640 * MEM];         // h (tf32-rounded), padded rows
__device__ float g_t32 [256 * MEM];         // t (tf32-rounded), padded rows
__device__ int   g_grp_nodes[NLVL][64];
__device__ int   g_grp_start[NLVL][50];

__device__ __forceinline__ float sigm(float v) {
    return __fdividef(1.0f, 1.0f + __expf(-v));
}
__device__ __forceinline__ float ftanh(float v) {
    return 1.0f - __fdividef(2.0f, __expf(2.0f * v) + 1.0f);
}
__device__ __forceinline__ float to_tf32(float x) {
    uint32_t u;
    asm("cvt.rna.tf32.f32 %0, %1;" : "=r"(u) : "f"(x));
    return __uint_as_float(u);
}

// =================== async-copy / mma helpers ================================
__device__ __forceinline__ uint32_t s2u(const void* p) {
    uint32_t a;
    asm("{ .reg .u64 t; cvta.to.shared.u64 t, %1; cvt.u32.u64 %0, t; }"
        : "=r"(a) : "l"(p));
    return a;
}
__device__ __forceinline__ void cpa16(uint32_t dst, const void* src) {
    asm volatile("cp.async.cg.shared.global [%0], [%1], 16;"
                 :: "r"(dst), "l"(src) : "memory");
}
__device__ __forceinline__ void cpa_commit() {
    asm volatile("cp.async.commit_group;" ::: "memory");
}
__device__ __forceinline__ void cpa_wait2() {
    asm volatile("cp.async.wait_group 2;" ::: "memory");
}
__device__ __forceinline__ void cpa_wait1() {
    asm volatile("cp.async.wait_group 1;" ::: "memory");
}
__device__ __forceinline__ void cpa_wait0() {
    asm volatile("cp.async.wait_group 0;" ::: "memory");
}
__device__ __forceinline__ void mma8(float* c, const uint32_t* a, const uint32_t* b) {
    asm volatile(
        "mma.sync.aligned.m16n8k8.row.col.f32.tf32.tf32.f32 "
        "{%0,%1,%2,%3}, {%4,%5,%6,%7}, {%8,%9}, {%0,%1,%2,%3};"
        : "+f"(c[0]), "+f"(c[1]), "+f"(c[2]), "+f"(c[3])
        : "r"(a[0]), "r"(a[1]), "r"(a[2]), "r"(a[3]), "r"(b[0]), "r"(b[1]));
}

// ====== multi-problem tf32 mma.sync split-K GEMM, 3-stage cp.async ==========
// Each launch carries up to 2 independent problems; blockIdx.x decodes
// (problem, bx, by, bz). For problem: C[z] = A[:, z-slice] @ B[:, z-slice]^T.
// K row stride is always 1024. fp32 fed raw to tf32 mma (hw truncation).
// No guards: A needs ny*BM readable rows; C slabs sized accordingly.
struct GP {
    const float* A; const float* B; float* C;
    int N, Klen, slab, nx, ny, nz;
};
#define SMSTRIDE 36
#define KSTRIDE  1024

template<int BM>
__global__ void __launch_bounds__(256) gemm2(GP p0, GP p1)
{
    constexpr int WM = BM / 2;
    constexpr int MF = BM / 32;
    constexpr int ASZ = BM * SMSTRIDE;
    constexpr int BSZ = 128 * SMSTRIDE;
    constexpr int STG = ASZ + BSZ;

    extern __shared__ float sm[];
    uint32_t uA[3], uB[3];
    #pragma unroll
    for (int s = 0; s < 3; s++) {
        uA[s] = s2u(sm + s * STG);
        uB[s] = s2u(sm + s * STG + ASZ);
    }

    // decode problem
    int bid = blockIdx.x;
    GP p = p0;
    int t0 = p0.nx * p0.ny * p0.nz;
    if (bid >= t0) { bid -= t0; p = p1; }
    int bx = bid % p.nx;
    int by = (bid / p.nx) % p.ny;
    int bz = bid / (p.nx * p.ny);

    int tid = threadIdx.x;
    int lane = tid & 31, wid = tid >> 5;
    int wm = wid >> 2, wn = wid & 3;
    int gr = lane >> 2, qc = lane & 3;
    int m0 = by * BM, n0 = bx * 128;
    int koff = bz * p.Klen;

    const float* Abase = p.A + (size_t)m0 * KSTRIDE + koff;
    const float* Bbase = p.B + (size_t)n0 * KSTRIDE + koff;
    float* C = p.C + (size_t)bz * p.slab;
    const int NCH = p.Klen >> 5;

    float cacc[MF][4][4];
    #pragma unroll
    for (int i = 0; i < MF; i++)
        #pragma unroll
        for (int j = 0; j < 4; j++)
            #pragma unroll
            for (int e = 0; e < 4; e++) cacc[i][j][e] = 0.f;

    auto load_chunk = [&](int c, int buf) {
        const float* Ap = Abase + c * 32;
        const float* Bp = Bbase + c * 32;
        #pragma unroll
        for (int i = 0; i < BM / 32; i++) {
            int id = tid + i * 256;
            int row = id >> 3, c4 = (id & 7) << 2;
            cpa16(uA[buf] + (row * SMSTRIDE + c4) * 4, Ap + (size_t)row * KSTRIDE + c4);
        }
        #pragma unroll
        for (int i = 0; i < 4; i++) {
            int id = tid + i * 256;
            int row = id >> 3, c4 = (id & 7) << 2;
            cpa16(uB[buf] + (row * SMSTRIDE + c4) * 4, Bp + (size_t)row * KSTRIDE + c4);
        }
        cpa_commit();
    };

    load_chunk(0, 0);
    if (NCH > 1) load_chunk(1, 1);

    for (int c = 0; c < NCH; c++) {
        int buf = c % 3;
        if (c + 2 < NCH) load_chunk(c + 2, (c + 2) % 3);
        int left = NCH - 1 - c;          // groups pending beyond chunk c
        if (left >= 2)      cpa_wait2();
        else if (left == 1) cpa_wait1();
        else                cpa_wait0();
        __syncthreads();

        const float* As = sm + buf * STG;
        const float* Bs = sm + buf * STG + ASZ;
        #pragma unroll
        for (int kk = 0; kk < 4; kk++) {
            int k = kk * 8;
            uint32_t b[4][2];
            #pragma unroll
            for (int ni = 0; ni < 4; ni++) {
                int nr = wn * 32 + ni * 8 + gr;
                b[ni][0] = __float_as_uint(Bs[nr * SMSTRIDE + k + qc]);
                b[ni][1] = __float_as_uint(Bs[nr * SMSTRIDE + k + qc + 4]);
            }
            uint32_t a[MF][4];
            #pragma unroll
            for (int mi = 0; mi < MF; mi++) {
                int mr = wm * WM + mi * 16 + gr;
                a[mi][0] = __float_as_uint(As[mr * SMSTRIDE + k + qc]);
                a[mi][1] = __float_as_uint(As[(mr + 8) * SMSTRIDE + k + qc]);
                a[mi][2] = __float_as_uint(As[mr * SMSTRIDE + k + qc + 4]);
                a[mi][3] = __float_as_uint(As[(mr + 8) * SMSTRIDE + k + qc + 4]);
            }
            #pragma unroll
            for (int mi = 0; mi < MF; mi++)
                #pragma unroll
                for (int ni = 0; ni < 4; ni++)
                    mma8(cacc[mi][ni], a[mi], b[ni]);
        }
        __syncthreads();
    }

    #pragma unroll
    for (int mi = 0; mi < MF; mi++)
        #pragma unroll
        for (int ni = 0; ni < 4; ni++) {
            int row = m0 + wm * WM + mi * 16 + gr;
            int col = n0 + wn * 32 + ni * 8 + qc * 2;
            *(float2*)(C + (size_t)row * p.N + col) =
                make_float2(cacc[mi][ni][0], cacc[mi][ni][1]);
            *(float2*)(C + (size_t)(row + 8) * p.N + col) =
                make_float2(cacc[mi][ni][2], cacc[mi][ni][3]);
        }
}

// ---------------- leaves: nodes 0..383 (XI = 2 partial slabs) ----------------
__global__ void leaf_k(float* __restrict__ h,
                       const float* __restrict__ ioux_b,
                       const float* __restrict__ iouh_b)
{
    int node = blockIdx.y;
    int j = blockIdx.x * 256 + threadIdx.x;
    const float* x0 = g_XIp + (size_t)node * TM3;
    const float* x1 = g_XIp + (size_t)NN * TM3 + (size_t)node * TM3;
    float ig = sigm(x0[j] + x1[j] + ioux_b[j] + iouh_b[j]);
    float og = sigm(x0[MEM + j] + x1[MEM + j] + ioux_b[MEM + j] + iouh_b[MEM + j]);
    float ug = ftanh(x0[2 * MEM + j] + x1[2 * MEM + j]
                     + ioux_b[2 * MEM + j] + iouh_b[2 * MEM + j]);
    float cv = ig * ug;
    size_t idx = (size_t)node * MEM + j;
    g_c[idx] = cv;
    float hv = og * ftanh(cv);
    h[idx] = hv;
    g_h32[idx] = to_tf32(hv);
}

// ---------------- one-time grouping by relation ------------------------------
__global__ void prep_groups(const int* __restrict__ rel_ids)
{
    const int lvl_n0[NLVL]  = {384, 427, 491, 507, 511};
    const int lvl_cnt[NLVL] = { 43,  64,  16,   4,   1};
    for (int L = 0; L < NLVL; L++) {
        int cnt_r[49];
        for (int r = 0; r < 49; r++) cnt_r[r] = 0;
        int n0 = lvl_n0[L], cnt = lvl_cnt[L];
        for (int i = 0; i < cnt; i++) cnt_r[rel_ids[n0 + i]]++;
        int acc = 0;
        for (int r = 0; r < 49; r++) { g_grp_start[L][r] = acc; acc += cnt_r[r]; }
        g_grp_start[L][49] = acc;
        int pos[49];
        for (int r = 0; r < 49; r++) pos[r] = g_grp_start[L][r];
        for (int i = 0; i < cnt; i++) {
            int r = rel_ids[n0 + i];
            g_grp_nodes[L][pos[r]++] = n0 + i - IBASE;
        }
    }
}

// --- t = (child-sum of h) @ Wrel[rel]^T; csum fused; rel==48 is identity -----
__global__ void __launch_bounds__(256) wrel_grp(const float* __restrict__ Wrel,
                                                const float* __restrict__ h,
                                                const int* __restrict__ child_idx,
                                                int lvl)
{
    int r  = blockIdx.y;
    int s0 = g_grp_start[lvl][r];
    int g  = g_grp_start[lvl][r + 1] - s0;
    if (g == 0) return;
    __shared__ float sh[MEM];
    int lane = threadIdx.x & 31, wid = threadIdx.x >> 5;
    int row = blockIdx.x * 8 + wid;
    bool ident = (r == 48);
    float4 w[8];
    if (!ident) {
        const float* W = Wrel + (size_t)r * (MEM * MEM) + (size_t)row * MEM;
        #pragma unroll
        for (int i = 0; i < 8; i++) w[i] = *(const float4*)(W + (i * 32 + lane) * 4);
    }
    for (int j = 0; j < g; j++) {
        int li = g_grp_nodes[lvl][s0 + j];
        int node = li + IBASE;
        const int* ci = child_idx + node * 4;
        int c0 = ci[0], c1 = ci[1], c2 = ci[2], c3 = ci[3];
        {   // fused child-sum (each thread one float4 of the 1024-vec)
            int i = threadIdx.x;
            float4 s = make_float4(0.f, 0.f, 0.f, 0.f);
            if (c0 >= 0) { float4 v = ((const float4*)(h + (size_t)c0 * MEM))[i];
                           s.x += v.x; s.y += v.y; s.z += v.z; s.w += v.w; }
            if (c1 >= 0) { float4 v = ((const float4*)(h + (size_t)c1 * MEM))[i];
                           s.x += v.x; s.y += v.y; s.z += v.z; s.w += v.w; }
            if (c2 >= 0) { float4 v = ((const float4*)(h + (size_t)c2 * MEM))[i];
                           s.x += v.x; s.y += v.y; s.z += v.z; s.w += v.w; }
            if (c3 >= 0) { float4 v = ((const float4*)(h + (size_t)c3 * MEM))[i];
                           s.x += v.x; s.y += v.y; s.z += v.z; s.w += v.w; }
            ((float4*)sh)[i] = s;
        }
        __syncthreads();
        float s;
        if (ident) {
            s = sh[row];
        } else {
            s = 0.f;
            #pragma unroll
            for (int i = 0; i < 8; i++) {
                int k4 = (i * 32 + lane) * 4;
                s += w[i].x * sh[k4] + w[i].y * sh[k4 + 1]
                   + w[i].z * sh[k4 + 2] + w[i].w * sh[k4 + 3];
            }
            #pragma unroll
            for (int o = 16; o; o >>= 1) s += __shfl_xor_sync(0xffffffffu, s, o);
        }
        if (lane == 0) g_t32[(size_t)li * MEM + row] = to_tf32(s);
        __syncthreads();
    }
}

// --- fused: fc from children + gates -> h, c (sums all partial slabs) --------
__global__ void cellfc_k(float* __restrict__ h,
                         const int* __restrict__ child_idx,
                         const float* __restrict__ ioux_b,
                         const float* __restrict__ iouh_b,
                         const float* __restrict__ fx_b,
                         const float* __restrict__ fh_b, int n0)
{
    int node = n0 + blockIdx.y;
    int li = node - IBASE;
    int j = blockIdx.x * 256 + threadIdx.x;
    const int* ci = child_idx + node * 4;

    float xf = 0.f;
    #pragma unroll
    for (int s = 0; s < 4; s++)
        xf += g_XFp[(size_t)s * (NINT * MEM) + (size_t)li * MEM + j];
    float base = xf + fx_b[j] + fh_b[j];

    float fc = 0.f;
    #pragma unroll
    for (int k = 0; k < 4; k++) {
        int c = ci[k];
        if (c >= 0) {
            float fh = 0.f;
            #pragma unroll
            for (int s = 0; s < 4; s++)
                fh += g_FHp[(size_t)s * (640 * MEM) + (size_t)c * MEM + j];
            fc += sigm(fh + base) * g_c[(size_t)c * MEM + j];
        }
    }

    float io0 = 0.f, io1 = 0.f, io2 = 0.f;
    #pragma unroll
    for (int s = 0; s < 4; s++) {
        const float* io = g_IOUp + (size_t)s * (64 * TM3) + (size_t)blockIdx.y * TM3;
        io0 += io[j]; io1 += io[MEM + j]; io2 += io[2 * MEM + j];
    }
    const float* x0 = g_XIp + (size_t)node * TM3;
    const float* x1 = g_XIp + (size_t)NN * TM3 + (size_t)node * TM3;

    float ig = sigm(io0 + x0[j] + x1[j] + ioux_b[j] + iouh_b[j]);
    float og = sigm(io1 + x0[MEM + j] + x1[MEM + j]
                    + ioux_b[MEM + j] + iouh_b[MEM + j]);
    float ug = ftanh(io2 + x0[2 * MEM + j] + x1[2 * MEM + j]
                     + ioux_b[2 * MEM + j] + iouh_b[2 * MEM + j]);
    float cv = ig * ug + fc;
    size_t idx = (size_t)node * MEM + j;
    g_c[idx] = cv;
    float hv = og * ftanh(cv);
    h[idx] = hv;
    g_h32[idx] = to_tf32(hv);
}

// ------------------------------- launcher ------------------------------------
extern "C" void kernel_launch(void* const* d_in, const int* in_sizes, int n_in,
                              void* d_out, int out_size)
{
    const float* x       = (const float*)d_in[0];
    const float* Wrel    = (const float*)d_in[1];
    const float* ioux_w  = (const float*)d_in[2];
    const float* ioux_b  = (const float*)d_in[3];
    const float* iouh_w  = (const float*)d_in[4];
    const float* iouh_b  = (const float*)d_in[5];
    const float* fx_w    = (const float*)d_in[6];
    const float* fx_b    = (const float*)d_in[7];
    const float* fh_w    = (const float*)d_in[8];
    const float* fh_b    = (const float*)d_in[9];
    const int*   child_idx = (const int*)d_in[10];
    const int*   rel_ids   = (const int*)d_in[11];
    float* h = (float*)d_out;

    const int SM128 = 3 * (128 + 128) * SMSTRIDE * 4;   // 110592 B
    const int SM64  = 3 * (64 + 128) * SMSTRIDE * 4;    //  82944 B
    cudaFuncSetAttribute(gemm2<128>, cudaFuncAttributeMaxDynamicSharedMemorySize, SM128);
    cudaFuncSetAttribute(gemm2<64>,  cudaFuncAttributeMaxDynamicSharedMemorySize, SM64);

    float *p_XIp, *p_XFp, *p_FHp, *p_IOUp, *p_h32, *p_t32;
    cudaGetSymbolAddress((void**)&p_XIp,  g_XIp);
    cudaGetSymbolAddress((void**)&p_XFp,  g_XFp);
    cudaGetSymbolAddress((void**)&p_FHp,  g_FHp);
    cudaGetSymbolAddress((void**)&p_IOUp, g_IOUp);
    cudaGetSymbolAddress((void**)&p_h32,  g_h32);
    cudaGetSymbolAddress((void**)&p_t32,  g_t32);

    prep_groups<<<1, 1>>>(rel_ids);

    // XI (512x3072, K=1024, split-K x2) + XF (128x1024, split-K x4) in one launch
    GP pXI = { x, ioux_w, p_XIp, TM3, 512, NN * TM3, 24, 4, 2 };
    GP pXF = { x + (size_t)IBASE * KD, fx_w, p_XFp, MEM, 256, NINT * MEM, 8, 1, 4 };
    gemm2<128><<<24 * 4 * 2 + 8 * 1 * 4, 256, SM128>>>(pXI, pXF);

    leaf_k<<<dim3(4, 384), 256>>>(h, ioux_b, iouh_b);

    const int lvl_n0[NLVL]  = {384, 427, 491, 507, 511};
    const int lvl_cnt[NLVL] = { 43,  64,  16,   4,   1};
    const GP pNone = { nullptr, nullptr, nullptr, 0, 0, 0, 0, 0, 0 };
    for (int L = 0; L < NLVL; L++) {
        int n0 = lvl_n0[L], cnt = lvl_cnt[L];
        wrel_grp<<<dim3(128, 49), 256>>>(Wrel, h, child_idx, L);

        // IOU(L) + FH(previous level) in one launch
        GP pIOU = { p_t32 + (size_t)(n0 - IBASE) * MEM, iouh_w, p_IOUp,
                    TM3, 256, 64 * TM3, 24, 1, 4 };
        GP pFH;
        if (L == 0)          // FH for all 384 leaves (6 x 64 rows)
            pFH = GP{ p_h32, fh_w, p_FHp, MEM, 256, 640 * MEM, 8, 6, 4 };
        else {               // FH for level L-1 nodes (64 padded rows)
            int np = lvl_n0[L - 1];
            pFH = GP{ p_h32 + (size_t)np * MEM, fh_w, p_FHp + (size_t)np * MEM,
                      MEM, 256, 640 * MEM, 8, 1, 4 };
        }
        int tot = pIOU.nx * pIOU.ny * pIOU.nz + pFH.nx * pFH.ny * pFH.nz;
        gemm2<64><<<tot, 256, SM64>>>(pIOU, pFH);

        cellfc_k<<<dim3(4, cnt), 256>>>(h, child_idx, ioux_b, iouh_b, fx_b, fh_b, n0);
    }
}